// round 13
// baseline (speedup 1.0000x reference)
#include <cuda_runtime.h>

#define NP     32768
#define HIDN   100
#define NSTEPS 100

// Per-j head weights, packed for uniform (constant-bank) access:
// cW[2j] = {w0,w1,w2,w3} = {Wdmu[j,0..2], Wds[j,0]}, cW[2j+1] = {w4,w5,-,-}.
__constant__ float4 cW[2 * HIDN];
__device__  float4 gWstage[2 * HIDN];

// ---------------------------------------------------------------------------
// Prep: stage packed head weights for the constant bank.
// ---------------------------------------------------------------------------
__global__ void prep_kernel(const float* __restrict__ Wdmu,
                            const float* __restrict__ Wds)
{
    const int j = threadIdx.x;
    if (j < HIDN) {
        gWstage[2 * j]     = make_float4(Wdmu[3 * j + 0], Wdmu[3 * j + 1],
                                         Wdmu[3 * j + 2], Wds[3 * j + 0]);
        gWstage[2 * j + 1] = make_float4(Wds[3 * j + 1], Wds[3 * j + 2], 0.f, 0.f);
    }
}

// ---------------------------------------------------------------------------
// Encoder: h1 = swish(x@We1+be1); h2 = swish(h1@We2+be2);
//          mu_zx = h2@Wmu+bmu ; log_t_zx = h2@Wlt+blt
// ---------------------------------------------------------------------------
__global__ void __launch_bounds__(128) encoder_kernel(
    const float* __restrict__ x,
    const float* __restrict__ We1, const float* __restrict__ be1,
    const float* __restrict__ We2, const float* __restrict__ be2,
    const float* __restrict__ Wmu, const float* __restrict__ bmu,
    const float* __restrict__ Wlt, const float* __restrict__ blt,
    float* __restrict__ out)
{
    extern __shared__ float sm[];
    float* sWe2 = sm;             // 10000
    float* sWe1 = sm + 10000;     // 300
    float* sbe1 = sm + 10300;     // 100
    float* sbe2 = sm + 10400;     // 100
    float* sWmu = sm + 10500;     // 200
    float* sWlt = sm + 10700;     // 100
    float* sh1  = sm + 10800;     // 128*101

    const int tid = threadIdx.x;
    for (int i = tid; i < HIDN * HIDN; i += 128) sWe2[i] = We2[i];
    for (int i = tid; i < 3 * HIDN; i += 128)    sWe1[i] = We1[i];
    if (tid < HIDN) {
        sbe1[tid] = be1[tid];
        sbe2[tid] = be2[tid];
        sWlt[tid] = Wlt[tid];
    }
    for (int i = tid; i < HIDN * 2; i += 128) sWmu[i] = Wmu[i];
    __syncthreads();

    const int p = blockIdx.x * 128 + tid;
    const float x0 = x[3 * p + 0];
    const float x1 = x[3 * p + 1];
    const float x2 = x[3 * p + 2];

    float* h1 = sh1 + tid * (HIDN + 1);   // stride 101: conflict-free

    #pragma unroll 4
    for (int k = 0; k < HIDN; k++) {
        float a = sbe1[k];
        a = fmaf(x0, sWe1[k], a);
        a = fmaf(x1, sWe1[HIDN + k], a);
        a = fmaf(x2, sWe1[2 * HIDN + k], a);
        float sig = __fdividef(1.f, 1.f + __expf(-a));
        h1[k] = a * sig;
    }

    float mu0 = bmu[0], mu1 = bmu[1], ltv = blt[0];
    for (int k = 0; k < HIDN; k++) {
        float a = sbe2[k];
        const float* w = sWe2 + k;
        #pragma unroll 4
        for (int j = 0; j < HIDN; j++)
            a = fmaf(h1[j], w[j * HIDN], a);
        float sig = __fdividef(1.f, 1.f + __expf(-a));
        float h2 = a * sig;
        mu0 = fmaf(h2, sWmu[2 * k + 0], mu0);
        mu1 = fmaf(h2, sWmu[2 * k + 1], mu1);
        ltv = fmaf(h2, sWlt[k], ltv);
    }

    out[8 * NP + 2 * p + 0] = mu0;
    out[8 * NP + 2 * p + 1] = mu1;
    out[10 * NP + p]        = ltv;
}

// ---------------------------------------------------------------------------
// SDE kernel v5: scalar accumulation (R7 structure), head weights sourced
// from __constant__ with uniform index -> LDCU/UR operands -> FFMA rt=1.
// Activation table stays in SMEM.
// ---------------------------------------------------------------------------
__global__ void __launch_bounds__(128) sde_kernel(
    const float* __restrict__ Wd1,  const float* __restrict__ bd1,
    const float* __restrict__ bdmu, const float* __restrict__ bds,
    const float* __restrict__ b_muz, const float* __restrict__ b_ltz,
    const float* __restrict__ noise,
    float* __restrict__ out)
{
    // tAct = {u0, u1, b, u0*u0}; tU = {u0*u1, u1*u1}
    __shared__ float4 tAct[HIDN];
    __shared__ float2 tU[HIDN];

    const int tid = threadIdx.x;
    for (int j = tid; j < HIDN; j += 128) {
        float u0 = Wd1[j];
        float u1 = Wd1[HIDN + j];
        float b  = bd1[j];
        tAct[j] = make_float4(u0, u1, b, u0 * u0);
        tU[j]   = make_float2(u0 * u1, u1 * u1);
    }
    __syncthreads();

    const int p = blockIdx.x * 128 + tid;

    float z0 = out[8 * NP + 2 * p + 0];
    float z1 = out[8 * NP + 2 * p + 1];
    const float ltv  = out[10 * NP + p];
    const float sqdt = sqrtf(__expf(2.f * ltv) * (1.0f / NSTEPS));

    const float2* __restrict__ noise2 = (const float2*)noise;

    for (int s = 0; s < NSTEPS; s++) {
        const float2 nz = noise2[s * NP + p];   // prefetch: overlap with j-loop

        float J[6][2];
        float Bm[6][3];
        #pragma unroll
        for (int i = 0; i < 6; i++) {
            J[i][0] = 0.f; J[i][1] = 0.f;
            Bm[i][0] = 0.f; Bm[i][1] = 0.f; Bm[i][2] = 0.f;
        }

        // ---- inner reduction over hidden units, 4 at a time ----
        for (int t = 0; t < HIDN / 4; t++) {
            const int j0 = 4 * t;

            // Stage 1: batched per-lane table loads (LDS) — activations only
            float4 A[4]; float2 U[4];
            #pragma unroll
            for (int q = 0; q < 4; q++) {
                A[q] = tAct[j0 + q];
                U[q] = tU[j0 + q];
            }

            // Stage 2: 4 independent activation chains
            float du0[4], du1[4], e00[4], e01[4], e11[4];
            #pragma unroll
            for (int q = 0; q < 4; q++) {
                float a   = fmaf(z0, A[q].x, fmaf(z1, A[q].y, A[q].z));
                float sig = __fdividef(1.f, 1.f + __expf(-a));
                float t1  = fmaf(-sig, sig, sig);                    // sig*(1-sig)
                float d   = fmaf(a, t1, sig);                        // swish'
                float e   = t1 * fmaf(a, fmaf(-2.f, sig, 1.f), 2.f); // swish''
                du0[q] = d * A[q].x;
                du1[q] = d * A[q].y;
                e00[q] = e * A[q].w;
                e01[q] = e * U[q].x;
                e11[q] = e * U[q].y;
            }

            // Stage 3: rank-1 accumulations; w_i from constant bank with a
            // uniform index -> UR operand -> banking-free FFMA (rt=1).
            #pragma unroll
            for (int q = 0; q < 4; q++) {
                const float4 wa = cW[2 * (j0 + q)];
                const float4 wb = cW[2 * (j0 + q) + 1];
                const float w[6] = { wa.x, wa.y, wa.z, wa.w, wb.x, wb.y };
                #pragma unroll
                for (int i = 0; i < 6; i++) {
                    J[i][0]  = fmaf(w[i], du0[q], J[i][0]);
                    J[i][1]  = fmaf(w[i], du1[q], J[i][1]);
                    Bm[i][0] = fmaf(w[i], e00[q], Bm[i][0]);
                    Bm[i][1] = fmaf(w[i], e01[q], Bm[i][1]);
                    Bm[i][2] = fmaf(w[i], e11[q], Bm[i][2]);
                }
            }
        }

        // ---- 2x2 geometry ----
        float g00 = 0.f, g01 = 0.f, g11 = 0.f;
        float Dg[2][2][2];
        #pragma unroll
        for (int k = 0; k < 2; k++)
            #pragma unroll
            for (int m = 0; m < 2; m++)
                #pragma unroll
                for (int l = 0; l < 2; l++)
                    Dg[k][m][l] = 0.f;

        #pragma unroll
        for (int i = 0; i < 6; i++) {
            g00 = fmaf(J[i][0], J[i][0], g00);
            g01 = fmaf(J[i][0], J[i][1], g01);
            g11 = fmaf(J[i][1], J[i][1], g11);
            #pragma unroll
            for (int k = 0; k < 2; k++)
                #pragma unroll
                for (int m = 0; m < 2; m++)
                    #pragma unroll
                    for (int l = 0; l < 2; l++)
                        Dg[k][m][l] += Bm[i][k + l] * J[i][m] + J[i][k] * Bm[i][m + l];
        }

        const float detg = fmaf(g00, g11, -g01 * g01);
        const float rin  = __fdividef(1.f, detg);
        float gi[2][2];
        gi[0][0] =  g11 * rin;
        gi[0][1] = -g01 * rin;
        gi[1][0] = -g01 * rin;
        gi[1][1] =  g00 * rin;

        float Ch[2][2][2];
        #pragma unroll
        for (int i = 0; i < 2; i++)
            #pragma unroll
            for (int k = 0; k < 2; k++)
                #pragma unroll
                for (int l = 0; l < 2; l++) {
                    float sacc = 0.f;
                    #pragma unroll
                    for (int m = 0; m < 2; m++)
                        sacc += gi[i][m] * (Dg[k][m][l] + Dg[l][m][k] - Dg[k][l][m]);
                    Ch[i][k][l] = 0.5f * sacc;
                }

        float drift[2];
        #pragma unroll
        for (int i = 0; i < 2; i++) {
            float sacc = 0.f;
            #pragma unroll
            for (int jj = 0; jj < 2; jj++)
                #pragma unroll
                for (int kk = 0; kk < 2; kk++)
                    sacc += gi[jj][kk] * Ch[i][jj][kk];
            drift[i] = 0.5f * sacc;
        }

        const float dW0 = sqdt * nz.x;
        const float dW1 = sqdt * nz.y;

        z0 += drift[0] + gi[0][0] * dW0 + gi[0][1] * dW1;
        z1 += drift[1] + gi[1][0] * dW0 + gi[1][1] * dW1;
    }

    // Final decoder heads at z
    float mu[3] = { bdmu[0], bdmu[1], bdmu[2] };
    float ls[3] = { bds[0],  bds[1],  bds[2]  };
    #pragma unroll 4
    for (int j = 0; j < HIDN; j++) {
        const float4 A  = tAct[j];
        const float4 wa = cW[2 * j];
        const float4 wb = cW[2 * j + 1];
        float a   = fmaf(z0, A.x, fmaf(z1, A.y, A.z));
        float sig = __fdividef(1.f, 1.f + __expf(-a));
        float h   = a * sig;
        mu[0] = fmaf(h, wa.x, mu[0]);
        mu[1] = fmaf(h, wa.y, mu[1]);
        mu[2] = fmaf(h, wa.z, mu[2]);
        ls[0] = fmaf(h, wa.w, ls[0]);
        ls[1] = fmaf(h, wb.x, ls[1]);
        ls[2] = fmaf(h, wb.y, ls[2]);
    }

    // Outputs: z | mu_xz | log_sigma_xz | mu_zx | log_t_zx | mu_z | log_t_z
    out[2 * p + 0] = z0;
    out[2 * p + 1] = z1;
    out[2 * NP + 3 * p + 0] = mu[0];
    out[2 * NP + 3 * p + 1] = mu[1];
    out[2 * NP + 3 * p + 2] = mu[2];
    out[5 * NP + 3 * p + 0] = ls[0];
    out[5 * NP + 3 * p + 1] = ls[1];
    out[5 * NP + 3 * p + 2] = ls[2];
    out[11 * NP + 2 * p + 0] = b_muz[0];
    out[11 * NP + 2 * p + 1] = b_muz[1];
    out[13 * NP + p] = b_ltz[0];
}

extern "C" void kernel_launch(void* const* d_in, const int* in_sizes, int n_in,
                              void* d_out, int out_size)
{
    const float* x     = (const float*)d_in[0];
    const float* We1   = (const float*)d_in[1];
    const float* be1   = (const float*)d_in[2];
    const float* We2   = (const float*)d_in[3];
    const float* be2   = (const float*)d_in[4];
    const float* Wmu   = (const float*)d_in[5];
    const float* bmu   = (const float*)d_in[6];
    const float* Wlt   = (const float*)d_in[7];
    const float* blt   = (const float*)d_in[8];
    const float* Wd1   = (const float*)d_in[9];
    const float* bd1   = (const float*)d_in[10];
    const float* Wdmu  = (const float*)d_in[11];
    const float* bdmu  = (const float*)d_in[12];
    const float* Wds   = (const float*)d_in[13];
    const float* bds   = (const float*)d_in[14];
    const float* b_muz = (const float*)d_in[15];
    const float* b_ltz = (const float*)d_in[16];
    const float* noise = (const float*)d_in[17];
    float* out = (float*)d_out;

    // Stage packed head weights, then copy into the constant bank
    // (device-to-device async memcpy: graph-capturable, no allocation).
    prep_kernel<<<1, 128>>>(Wdmu, Wds);
    void* stage_addr = nullptr;
    void* const_addr = nullptr;
    cudaGetSymbolAddress(&stage_addr, gWstage);
    cudaGetSymbolAddress(&const_addr, cW);
    cudaMemcpyAsync(const_addr, stage_addr, sizeof(float4) * 2 * HIDN,
                    cudaMemcpyDeviceToDevice, 0);

    const size_t smem = (size_t)(10800 + 128 * (HIDN + 1)) * sizeof(float); // ~94.9 KB
    cudaFuncSetAttribute(encoder_kernel,
                         cudaFuncAttributeMaxDynamicSharedMemorySize, (int)smem);

    encoder_kernel<<<NP / 128, 128, smem>>>(x, We1, be1, We2, be2,
                                            Wmu, bmu, Wlt, blt, out);
    sde_kernel<<<NP / 128, 128>>>(Wd1, bd1, bdmu, bds,
                                  b_muz, b_ltz, noise, out);
}

// round 15
// speedup vs baseline: 1.0018x; 1.0018x over previous
#include <cuda_runtime.h>

#define NP     32768
#define HIDN   100
#define NSTEPS 100

// ---------------------------------------------------------------------------
// Encoder: h1 = swish(x@We1+be1); h2 = swish(h1@We2+be2);
//          mu_zx = h2@Wmu+bmu ; log_t_zx = h2@Wlt+blt
// ---------------------------------------------------------------------------
__global__ void __launch_bounds__(128) encoder_kernel(
    const float* __restrict__ x,
    const float* __restrict__ We1, const float* __restrict__ be1,
    const float* __restrict__ We2, const float* __restrict__ be2,
    const float* __restrict__ Wmu, const float* __restrict__ bmu,
    const float* __restrict__ Wlt, const float* __restrict__ blt,
    float* __restrict__ out)
{
    extern __shared__ float sm[];
    float* sWe2 = sm;             // 10000
    float* sWe1 = sm + 10000;     // 300
    float* sbe1 = sm + 10300;     // 100
    float* sbe2 = sm + 10400;     // 100
    float* sWmu = sm + 10500;     // 200
    float* sWlt = sm + 10700;     // 100
    float* sh1  = sm + 10800;     // 128*101

    const int tid = threadIdx.x;
    for (int i = tid; i < HIDN * HIDN; i += 128) sWe2[i] = We2[i];
    for (int i = tid; i < 3 * HIDN; i += 128)    sWe1[i] = We1[i];
    if (tid < HIDN) {
        sbe1[tid] = be1[tid];
        sbe2[tid] = be2[tid];
        sWlt[tid] = Wlt[tid];
    }
    for (int i = tid; i < HIDN * 2; i += 128) sWmu[i] = Wmu[i];
    __syncthreads();

    const int p = blockIdx.x * 128 + tid;
    const float x0 = x[3 * p + 0];
    const float x1 = x[3 * p + 1];
    const float x2 = x[3 * p + 2];

    float* h1 = sh1 + tid * (HIDN + 1);   // stride 101: conflict-free

    #pragma unroll 4
    for (int k = 0; k < HIDN; k++) {
        float a = sbe1[k];
        a = fmaf(x0, sWe1[k], a);
        a = fmaf(x1, sWe1[HIDN + k], a);
        a = fmaf(x2, sWe1[2 * HIDN + k], a);
        float sig = __fdividef(1.f, 1.f + __expf(-a));
        h1[k] = a * sig;
    }

    float mu0 = bmu[0], mu1 = bmu[1], ltv = blt[0];
    for (int k = 0; k < HIDN; k++) {
        float a = sbe2[k];
        const float* w = sWe2 + k;
        #pragma unroll 4
        for (int j = 0; j < HIDN; j++)
            a = fmaf(h1[j], w[j * HIDN], a);
        float sig = __fdividef(1.f, 1.f + __expf(-a));
        float h2 = a * sig;
        mu0 = fmaf(h2, sWmu[2 * k + 0], mu0);
        mu1 = fmaf(h2, sWmu[2 * k + 1], mu1);
        ltv = fmaf(h2, sWlt[k], ltv);
    }

    out[8 * NP + 2 * p + 0] = mu0;
    out[8 * NP + 2 * p + 1] = mu1;
    out[10 * NP + p]        = ltv;
}

// ---------------------------------------------------------------------------
// SDE kernel v6: 1 thread/point. Per-j moment coefficients w_i*u_l (12) and
// w_i*uu_q (18) are PRECOMPUTED into SMEM tables, so each accumulation FMA
// multiplies a table value by only d (swish') or e (swish''): the 5 product
// MULs per j are gone -> 39 fma-pipe slots/j instead of 44 on the rt=2
// banking roofline.
// ---------------------------------------------------------------------------
__global__ void __launch_bounds__(128) sde_kernel(
    const float* __restrict__ Wd1,  const float* __restrict__ bd1,
    const float* __restrict__ Wdmu, const float* __restrict__ bdmu,
    const float* __restrict__ Wds,  const float* __restrict__ bds,
    const float* __restrict__ b_muz, const float* __restrict__ b_ltz,
    const float* __restrict__ noise,
    float* __restrict__ out)
{
    // tAct = {u0, u1, b, -}
    // tJ4[j][0..2]: w_i*u_l, (i,l) pairs: {i0l0,i0l1,i1l0,i1l1},{i2..i3},{i4..i5}
    // tB4[j][0..4]: w_i*uu_q, (i,q): {00,01,02,10},{11,12,20,21},{22,30,31,32},
    //                                {40,41,42,50},{51,52,-,-}
    // tWa/tWb: raw head weights for the final decoder pass.
    __shared__ float4 tAct[HIDN];
    __shared__ float4 tJ4[HIDN][3];
    __shared__ float4 tB4[HIDN][5];
    __shared__ float4 tWa[HIDN];
    __shared__ float2 tWb[HIDN];

    const int tid = threadIdx.x;
    for (int j = tid; j < HIDN; j += 128) {
        float u0 = Wd1[j];
        float u1 = Wd1[HIDN + j];
        float b  = bd1[j];
        tAct[j] = make_float4(u0, u1, b, 0.f);
        float w0 = Wdmu[3 * j + 0], w1 = Wdmu[3 * j + 1], w2 = Wdmu[3 * j + 2];
        float w3 = Wds[3 * j + 0],  w4 = Wds[3 * j + 1],  w5 = Wds[3 * j + 2];
        tWa[j] = make_float4(w0, w1, w2, w3);
        tWb[j] = make_float2(w4, w5);
        tJ4[j][0] = make_float4(w0 * u0, w0 * u1, w1 * u0, w1 * u1);
        tJ4[j][1] = make_float4(w2 * u0, w2 * u1, w3 * u0, w3 * u1);
        tJ4[j][2] = make_float4(w4 * u0, w4 * u1, w5 * u0, w5 * u1);
        float uu0 = u0 * u0, uu1 = u0 * u1, uu2 = u1 * u1;
        tB4[j][0] = make_float4(w0 * uu0, w0 * uu1, w0 * uu2, w1 * uu0);
        tB4[j][1] = make_float4(w1 * uu1, w1 * uu2, w2 * uu0, w2 * uu1);
        tB4[j][2] = make_float4(w2 * uu2, w3 * uu0, w3 * uu1, w3 * uu2);
        tB4[j][3] = make_float4(w4 * uu0, w4 * uu1, w4 * uu2, w5 * uu0);
        tB4[j][4] = make_float4(w5 * uu1, w5 * uu2, 0.f, 0.f);
    }
    __syncthreads();

    const int p = blockIdx.x * 128 + tid;

    float z0 = out[8 * NP + 2 * p + 0];
    float z1 = out[8 * NP + 2 * p + 1];
    const float ltv  = out[10 * NP + p];
    const float sqdt = sqrtf(__expf(2.f * ltv) * (1.0f / NSTEPS));

    const float2* __restrict__ noise2 = (const float2*)noise;

    for (int s = 0; s < NSTEPS; s++) {
        const float2 nz = noise2[s * NP + p];   // prefetch: overlap with j-loop

        float J[6][2];
        float Bm[6][3];
        #pragma unroll
        for (int i = 0; i < 6; i++) {
            J[i][0] = 0.f; J[i][1] = 0.f;
            Bm[i][0] = 0.f; Bm[i][1] = 0.f; Bm[i][2] = 0.f;
        }

        // ---- inner reduction over hidden units, 4 at a time ----
        for (int t = 0; t < HIDN / 4; t++) {
            const int j0 = 4 * t;

            // Stage 1+2: 4 independent activation chains -> d, e only
            float d[4], e[4];
            #pragma unroll
            for (int q = 0; q < 4; q++) {
                const float4 A = tAct[j0 + q];
                float a   = fmaf(z0, A.x, fmaf(z1, A.y, A.z));
                float sig = __fdividef(1.f, 1.f + __expf(-a));
                float t1  = fmaf(-sig, sig, sig);                    // sig*(1-sig)
                d[q] = fmaf(a, t1, sig);                             // swish'
                e[q] = t1 * fmaf(a, fmaf(-2.f, sig, 1.f), 2.f);      // swish''
            }

            // Stage 3: table-driven accumulation (30 FMA/j, no product MULs)
            #pragma unroll
            for (int q = 0; q < 4; q++) {
                const int j = j0 + q;
                const float dq = d[q], eq = e[q];
                const float4 p0 = tJ4[j][0];
                const float4 p1 = tJ4[j][1];
                const float4 p2 = tJ4[j][2];
                J[0][0] = fmaf(p0.x, dq, J[0][0]);
                J[0][1] = fmaf(p0.y, dq, J[0][1]);
                J[1][0] = fmaf(p0.z, dq, J[1][0]);
                J[1][1] = fmaf(p0.w, dq, J[1][1]);
                J[2][0] = fmaf(p1.x, dq, J[2][0]);
                J[2][1] = fmaf(p1.y, dq, J[2][1]);
                J[3][0] = fmaf(p1.z, dq, J[3][0]);
                J[3][1] = fmaf(p1.w, dq, J[3][1]);
                J[4][0] = fmaf(p2.x, dq, J[4][0]);
                J[4][1] = fmaf(p2.y, dq, J[4][1]);
                J[5][0] = fmaf(p2.z, dq, J[5][0]);
                J[5][1] = fmaf(p2.w, dq, J[5][1]);
                const float4 b0 = tB4[j][0];
                const float4 b1 = tB4[j][1];
                const float4 b2 = tB4[j][2];
                const float4 b3 = tB4[j][3];
                const float4 b4 = tB4[j][4];
                Bm[0][0] = fmaf(b0.x, eq, Bm[0][0]);
                Bm[0][1] = fmaf(b0.y, eq, Bm[0][1]);
                Bm[0][2] = fmaf(b0.z, eq, Bm[0][2]);
                Bm[1][0] = fmaf(b0.w, eq, Bm[1][0]);
                Bm[1][1] = fmaf(b1.x, eq, Bm[1][1]);
                Bm[1][2] = fmaf(b1.y, eq, Bm[1][2]);
                Bm[2][0] = fmaf(b1.z, eq, Bm[2][0]);
                Bm[2][1] = fmaf(b1.w, eq, Bm[2][1]);
                Bm[2][2] = fmaf(b2.x, eq, Bm[2][2]);
                Bm[3][0] = fmaf(b2.y, eq, Bm[3][0]);
                Bm[3][1] = fmaf(b2.z, eq, Bm[3][1]);
                Bm[3][2] = fmaf(b2.w, eq, Bm[3][2]);
                Bm[4][0] = fmaf(b3.x, eq, Bm[4][0]);
                Bm[4][1] = fmaf(b3.y, eq, Bm[4][1]);
                Bm[4][2] = fmaf(b3.z, eq, Bm[4][2]);
                Bm[5][0] = fmaf(b3.w, eq, Bm[5][0]);
                Bm[5][1] = fmaf(b4.x, eq, Bm[5][1]);
                Bm[5][2] = fmaf(b4.y, eq, Bm[5][2]);
            }
        }

        // ---- 2x2 geometry ----
        // G and C[q][m] = sum_i Bm[i][q] * J[i][m]; Dg[k][m][l] = C[k+l][m]+C[m+l][k]
        float g00 = 0.f, g01 = 0.f, g11 = 0.f;
        float C[3][2];
        C[0][0] = C[0][1] = C[1][0] = C[1][1] = C[2][0] = C[2][1] = 0.f;

        #pragma unroll
        for (int i = 0; i < 6; i++) {
            g00 = fmaf(J[i][0], J[i][0], g00);
            g01 = fmaf(J[i][0], J[i][1], g01);
            g11 = fmaf(J[i][1], J[i][1], g11);
            #pragma unroll
            for (int q = 0; q < 3; q++) {
                C[q][0] = fmaf(Bm[i][q], J[i][0], C[q][0]);
                C[q][1] = fmaf(Bm[i][q], J[i][1], C[q][1]);
            }
        }

        float Dg[2][2][2];
        #pragma unroll
        for (int k = 0; k < 2; k++)
            #pragma unroll
            for (int m = 0; m < 2; m++)
                #pragma unroll
                for (int l = 0; l < 2; l++)
                    Dg[k][m][l] = C[k + l][m] + C[m + l][k];

        const float detg = fmaf(g00, g11, -g01 * g01);
        const float rin  = __fdividef(1.f, detg);
        float gi[2][2];
        gi[0][0] =  g11 * rin;
        gi[0][1] = -g01 * rin;
        gi[1][0] = -g01 * rin;
        gi[1][1] =  g00 * rin;

        float Ch[2][2][2];
        #pragma unroll
        for (int i = 0; i < 2; i++)
            #pragma unroll
            for (int k = 0; k < 2; k++)
                #pragma unroll
                for (int l = 0; l < 2; l++) {
                    float sacc = 0.f;
                    #pragma unroll
                    for (int m = 0; m < 2; m++)
                        sacc += gi[i][m] * (Dg[k][m][l] + Dg[l][m][k] - Dg[k][l][m]);
                    Ch[i][k][l] = 0.5f * sacc;
                }

        float drift[2];
        #pragma unroll
        for (int i = 0; i < 2; i++) {
            float sacc = 0.f;
            #pragma unroll
            for (int jj = 0; jj < 2; jj++)
                #pragma unroll
                for (int kk = 0; kk < 2; kk++)
                    sacc += gi[jj][kk] * Ch[i][jj][kk];
            drift[i] = 0.5f * sacc;
        }

        const float dW0 = sqdt * nz.x;
        const float dW1 = sqdt * nz.y;

        z0 += drift[0] + gi[0][0] * dW0 + gi[0][1] * dW1;
        z1 += drift[1] + gi[1][0] * dW0 + gi[1][1] * dW1;
    }

    // Final decoder heads at z
    float mu[3] = { bdmu[0], bdmu[1], bdmu[2] };
    float ls[3] = { bds[0],  bds[1],  bds[2]  };
    #pragma unroll 4
    for (int j = 0; j < HIDN; j++) {
        const float4 A  = tAct[j];
        const float4 wa = tWa[j];
        const float2 wb = tWb[j];
        float a   = fmaf(z0, A.x, fmaf(z1, A.y, A.z));
        float sig = __fdividef(1.f, 1.f + __expf(-a));
        float h   = a * sig;
        mu[0] = fmaf(h, wa.x, mu[0]);
        mu[1] = fmaf(h, wa.y, mu[1]);
        mu[2] = fmaf(h, wa.z, mu[2]);
        ls[0] = fmaf(h, wa.w, ls[0]);
        ls[1] = fmaf(h, wb.x, ls[1]);
        ls[2] = fmaf(h, wb.y, ls[2]);
    }

    // Outputs: z | mu_xz | log_sigma_xz | mu_zx | log_t_zx | mu_z | log_t_z
    out[2 * p + 0] = z0;
    out[2 * p + 1] = z1;
    out[2 * NP + 3 * p + 0] = mu[0];
    out[2 * NP + 3 * p + 1] = mu[1];
    out[2 * NP + 3 * p + 2] = mu[2];
    out[5 * NP + 3 * p + 0] = ls[0];
    out[5 * NP + 3 * p + 1] = ls[1];
    out[5 * NP + 3 * p + 2] = ls[2];
    out[11 * NP + 2 * p + 0] = b_muz[0];
    out[11 * NP + 2 * p + 1] = b_muz[1];
    out[13 * NP + p] = b_ltz[0];
}

extern "C" void kernel_launch(void* const* d_in, const int* in_sizes, int n_in,
                              void* d_out, int out_size)
{
    const float* x     = (const float*)d_in[0];
    const float* We1   = (const float*)d_in[1];
    const float* be1   = (const float*)d_in[2];
    const float* We2   = (const float*)d_in[3];
    const float* be2   = (const float*)d_in[4];
    const float* Wmu   = (const float*)d_in[5];
    const float* bmu   = (const float*)d_in[6];
    const float* Wlt   = (const float*)d_in[7];
    const float* blt   = (const float*)d_in[8];
    const float* Wd1   = (const float*)d_in[9];
    const float* bd1   = (const float*)d_in[10];
    const float* Wdmu  = (const float*)d_in[11];
    const float* bdmu  = (const float*)d_in[12];
    const float* Wds   = (const float*)d_in[13];
    const float* bds   = (const float*)d_in[14];
    const float* b_muz = (const float*)d_in[15];
    const float* b_ltz = (const float*)d_in[16];
    const float* noise = (const float*)d_in[17];
    float* out = (float*)d_out;

    const size_t smem = (size_t)(10800 + 128 * (HIDN + 1)) * sizeof(float); // ~94.9 KB
    cudaFuncSetAttribute(encoder_kernel,
                         cudaFuncAttributeMaxDynamicSharedMemorySize, (int)smem);

    encoder_kernel<<<NP / 128, 128, smem>>>(x, We1, be1, We2, be2,
                                            Wmu, bmu, Wlt, blt, out);
    sde_kernel<<<NP / 128, 128>>>(Wd1, bd1, Wdmu, bdmu, Wds, bds,
                                  b_muz, b_ltz, noise, out);
}

// round 16
// speedup vs baseline: 1.1083x; 1.1063x over previous
#include <cuda_runtime.h>

#define NP     32768
#define HIDN   100
#define NSTEPS 100

// ---------------------------------------------------------------------------
// Encoder: h1 = swish(x@We1+be1); h2 = swish(h1@We2+be2);
//          mu_zx = h2@Wmu+bmu ; log_t_zx = h2@Wlt+blt
// ---------------------------------------------------------------------------
__global__ void __launch_bounds__(128) encoder_kernel(
    const float* __restrict__ x,
    const float* __restrict__ We1, const float* __restrict__ be1,
    const float* __restrict__ We2, const float* __restrict__ be2,
    const float* __restrict__ Wmu, const float* __restrict__ bmu,
    const float* __restrict__ Wlt, const float* __restrict__ blt,
    float* __restrict__ out)
{
    extern __shared__ float sm[];
    float* sWe2 = sm;             // 10000
    float* sWe1 = sm + 10000;     // 300
    float* sbe1 = sm + 10300;     // 100
    float* sbe2 = sm + 10400;     // 100
    float* sWmu = sm + 10500;     // 200
    float* sWlt = sm + 10700;     // 100
    float* sh1  = sm + 10800;     // 128*101

    const int tid = threadIdx.x;
    for (int i = tid; i < HIDN * HIDN; i += 128) sWe2[i] = We2[i];
    for (int i = tid; i < 3 * HIDN; i += 128)    sWe1[i] = We1[i];
    if (tid < HIDN) {
        sbe1[tid] = be1[tid];
        sbe2[tid] = be2[tid];
        sWlt[tid] = Wlt[tid];
    }
    for (int i = tid; i < HIDN * 2; i += 128) sWmu[i] = Wmu[i];
    __syncthreads();

    const int p = blockIdx.x * 128 + tid;
    const float x0 = x[3 * p + 0];
    const float x1 = x[3 * p + 1];
    const float x2 = x[3 * p + 2];

    float* h1 = sh1 + tid * (HIDN + 1);   // stride 101: conflict-free

    #pragma unroll 4
    for (int k = 0; k < HIDN; k++) {
        float a = sbe1[k];
        a = fmaf(x0, sWe1[k], a);
        a = fmaf(x1, sWe1[HIDN + k], a);
        a = fmaf(x2, sWe1[2 * HIDN + k], a);
        float sig = __fdividef(1.f, 1.f + __expf(-a));
        h1[k] = a * sig;
    }

    float mu0 = bmu[0], mu1 = bmu[1], ltv = blt[0];
    for (int k = 0; k < HIDN; k++) {
        float a = sbe2[k];
        const float* w = sWe2 + k;
        #pragma unroll 4
        for (int j = 0; j < HIDN; j++)
            a = fmaf(h1[j], w[j * HIDN], a);
        float sig = __fdividef(1.f, 1.f + __expf(-a));
        float h2 = a * sig;
        mu0 = fmaf(h2, sWmu[2 * k + 0], mu0);
        mu1 = fmaf(h2, sWmu[2 * k + 1], mu1);
        ltv = fmaf(h2, sWlt[k], ltv);
    }

    out[8 * NP + 2 * p + 0] = mu0;
    out[8 * NP + 2 * p + 1] = mu1;
    out[10 * NP + p]        = ltv;
}

// ---------------------------------------------------------------------------
// SDE kernel v7: 1 thread/point. Only the 12 J-coefficients p[i][l]=w_i*u_l
// are tabulated (3 LDS.128/j + 1 for activation data = 4/j, half of v6).
// The 18 B accumulations reuse the J table via e-scaled broadcasts:
//   Bm[i][0] += p[i][0]*eu0 ; Bm[i][1] += p[i][0]*eu1 ; Bm[i][2] += p[i][1]*eu1
// with eu0 = e*u0, eu1 = e*u1 (2 extra MULs/j). 41 fma slots/j.
// ---------------------------------------------------------------------------
__global__ void __launch_bounds__(128) sde_kernel(
    const float* __restrict__ Wd1,  const float* __restrict__ bd1,
    const float* __restrict__ Wdmu, const float* __restrict__ bdmu,
    const float* __restrict__ Wds,  const float* __restrict__ bds,
    const float* __restrict__ b_muz, const float* __restrict__ b_ltz,
    const float* __restrict__ noise,
    float* __restrict__ out)
{
    // sTab[j][0] = {u0, u1, b, 0}
    // sTab[j][1] = {w0u0, w0u1, w1u0, w1u1}
    // sTab[j][2] = {w2u0, w2u1, w3u0, w3u1}
    // sTab[j][3] = {w4u0, w4u1, w5u0, w5u1}
    __shared__ float4 sTab[HIDN][4];
    __shared__ float4 tWa[HIDN];   // raw head weights for final decoder pass
    __shared__ float2 tWb[HIDN];

    const int tid = threadIdx.x;
    for (int j = tid; j < HIDN; j += 128) {
        float u0 = Wd1[j];
        float u1 = Wd1[HIDN + j];
        float b  = bd1[j];
        float w0 = Wdmu[3 * j + 0], w1 = Wdmu[3 * j + 1], w2 = Wdmu[3 * j + 2];
        float w3 = Wds[3 * j + 0],  w4 = Wds[3 * j + 1],  w5 = Wds[3 * j + 2];
        sTab[j][0] = make_float4(u0, u1, b, 0.f);
        sTab[j][1] = make_float4(w0 * u0, w0 * u1, w1 * u0, w1 * u1);
        sTab[j][2] = make_float4(w2 * u0, w2 * u1, w3 * u0, w3 * u1);
        sTab[j][3] = make_float4(w4 * u0, w4 * u1, w5 * u0, w5 * u1);
        tWa[j] = make_float4(w0, w1, w2, w3);
        tWb[j] = make_float2(w4, w5);
    }
    __syncthreads();

    const int p = blockIdx.x * 128 + tid;

    float z0 = out[8 * NP + 2 * p + 0];
    float z1 = out[8 * NP + 2 * p + 1];
    const float ltv  = out[10 * NP + p];
    const float sqdt = sqrtf(__expf(2.f * ltv) * (1.0f / NSTEPS));

    const float2* __restrict__ noise2 = (const float2*)noise;

    for (int s = 0; s < NSTEPS; s++) {
        const float2 nz = noise2[s * NP + p];   // prefetch: overlap with j-loop

        float J[6][2];
        float Bm[6][3];
        #pragma unroll
        for (int i = 0; i < 6; i++) {
            J[i][0] = 0.f; J[i][1] = 0.f;
            Bm[i][0] = 0.f; Bm[i][1] = 0.f; Bm[i][2] = 0.f;
        }

        // ---- inner reduction over hidden units, 4 at a time ----
        for (int t = 0; t < HIDN / 4; t++) {
            const int j0 = 4 * t;

            // Stage 1+2: 4 independent activation chains -> d, eu0, eu1
            float d[4], eu0[4], eu1[4];
            #pragma unroll
            for (int q = 0; q < 4; q++) {
                const float4 A = sTab[j0 + q][0];
                float a   = fmaf(z0, A.x, fmaf(z1, A.y, A.z));
                float sig = __fdividef(1.f, 1.f + __expf(-a));
                float t1  = fmaf(-sig, sig, sig);                    // sig*(1-sig)
                d[q] = fmaf(a, t1, sig);                             // swish'
                float e = t1 * fmaf(a, fmaf(-2.f, sig, 1.f), 2.f);   // swish''
                eu0[q] = e * A.x;
                eu1[q] = e * A.y;
            }

            // Stage 3: table-driven accumulation (30 FMA/j, 3 LDS.128/j)
            #pragma unroll
            for (int q = 0; q < 4; q++) {
                const int j = j0 + q;
                const float dq = d[q], e0 = eu0[q], e1 = eu1[q];
                const float4 p0 = sTab[j][1];
                const float4 p1 = sTab[j][2];
                const float4 p2 = sTab[j][3];
                // heads 0,1
                J[0][0]  = fmaf(p0.x, dq, J[0][0]);
                J[0][1]  = fmaf(p0.y, dq, J[0][1]);
                Bm[0][0] = fmaf(p0.x, e0, Bm[0][0]);
                Bm[0][1] = fmaf(p0.x, e1, Bm[0][1]);
                Bm[0][2] = fmaf(p0.y, e1, Bm[0][2]);
                J[1][0]  = fmaf(p0.z, dq, J[1][0]);
                J[1][1]  = fmaf(p0.w, dq, J[1][1]);
                Bm[1][0] = fmaf(p0.z, e0, Bm[1][0]);
                Bm[1][1] = fmaf(p0.z, e1, Bm[1][1]);
                Bm[1][2] = fmaf(p0.w, e1, Bm[1][2]);
                // heads 2,3
                J[2][0]  = fmaf(p1.x, dq, J[2][0]);
                J[2][1]  = fmaf(p1.y, dq, J[2][1]);
                Bm[2][0] = fmaf(p1.x, e0, Bm[2][0]);
                Bm[2][1] = fmaf(p1.x, e1, Bm[2][1]);
                Bm[2][2] = fmaf(p1.y, e1, Bm[2][2]);
                J[3][0]  = fmaf(p1.z, dq, J[3][0]);
                J[3][1]  = fmaf(p1.w, dq, J[3][1]);
                Bm[3][0] = fmaf(p1.z, e0, Bm[3][0]);
                Bm[3][1] = fmaf(p1.z, e1, Bm[3][1]);
                Bm[3][2] = fmaf(p1.w, e1, Bm[3][2]);
                // heads 4,5
                J[4][0]  = fmaf(p2.x, dq, J[4][0]);
                J[4][1]  = fmaf(p2.y, dq, J[4][1]);
                Bm[4][0] = fmaf(p2.x, e0, Bm[4][0]);
                Bm[4][1] = fmaf(p2.x, e1, Bm[4][1]);
                Bm[4][2] = fmaf(p2.y, e1, Bm[4][2]);
                J[5][0]  = fmaf(p2.z, dq, J[5][0]);
                J[5][1]  = fmaf(p2.w, dq, J[5][1]);
                Bm[5][0] = fmaf(p2.z, e0, Bm[5][0]);
                Bm[5][1] = fmaf(p2.z, e1, Bm[5][1]);
                Bm[5][2] = fmaf(p2.w, e1, Bm[5][2]);
            }
        }

        // ---- 2x2 geometry ----
        // G and C[q][m] = sum_i Bm[i][q] * J[i][m]; Dg[k][m][l] = C[k+l][m]+C[m+l][k]
        float g00 = 0.f, g01 = 0.f, g11 = 0.f;
        float C[3][2];
        C[0][0] = C[0][1] = C[1][0] = C[1][1] = C[2][0] = C[2][1] = 0.f;

        #pragma unroll
        for (int i = 0; i < 6; i++) {
            g00 = fmaf(J[i][0], J[i][0], g00);
            g01 = fmaf(J[i][0], J[i][1], g01);
            g11 = fmaf(J[i][1], J[i][1], g11);
            #pragma unroll
            for (int q = 0; q < 3; q++) {
                C[q][0] = fmaf(Bm[i][q], J[i][0], C[q][0]);
                C[q][1] = fmaf(Bm[i][q], J[i][1], C[q][1]);
            }
        }

        float Dg[2][2][2];
        #pragma unroll
        for (int k = 0; k < 2; k++)
            #pragma unroll
            for (int m = 0; m < 2; m++)
                #pragma unroll
                for (int l = 0; l < 2; l++)
                    Dg[k][m][l] = C[k + l][m] + C[m + l][k];

        const float detg = fmaf(g00, g11, -g01 * g01);
        const float rin  = __fdividef(1.f, detg);
        float gi[2][2];
        gi[0][0] =  g11 * rin;
        gi[0][1] = -g01 * rin;
        gi[1][0] = -g01 * rin;
        gi[1][1] =  g00 * rin;

        float Ch[2][2][2];
        #pragma unroll
        for (int i = 0; i < 2; i++)
            #pragma unroll
            for (int k = 0; k < 2; k++)
                #pragma unroll
                for (int l = 0; l < 2; l++) {
                    float sacc = 0.f;
                    #pragma unroll
                    for (int m = 0; m < 2; m++)
                        sacc += gi[i][m] * (Dg[k][m][l] + Dg[l][m][k] - Dg[k][l][m]);
                    Ch[i][k][l] = 0.5f * sacc;
                }

        float drift[2];
        #pragma unroll
        for (int i = 0; i < 2; i++) {
            float sacc = 0.f;
            #pragma unroll
            for (int jj = 0; jj < 2; jj++)
                #pragma unroll
                for (int kk = 0; kk < 2; kk++)
                    sacc += gi[jj][kk] * Ch[i][jj][kk];
            drift[i] = 0.5f * sacc;
        }

        const float dW0 = sqdt * nz.x;
        const float dW1 = sqdt * nz.y;

        z0 += drift[0] + gi[0][0] * dW0 + gi[0][1] * dW1;
        z1 += drift[1] + gi[1][0] * dW0 + gi[1][1] * dW1;
    }

    // Final decoder heads at z
    float mu[3] = { bdmu[0], bdmu[1], bdmu[2] };
    float ls[3] = { bds[0],  bds[1],  bds[2]  };
    #pragma unroll 4
    for (int j = 0; j < HIDN; j++) {
        const float4 A  = sTab[j][0];
        const float4 wa = tWa[j];
        const float2 wb = tWb[j];
        float a   = fmaf(z0, A.x, fmaf(z1, A.y, A.z));
        float sig = __fdividef(1.f, 1.f + __expf(-a));
        float h   = a * sig;
        mu[0] = fmaf(h, wa.x, mu[0]);
        mu[1] = fmaf(h, wa.y, mu[1]);
        mu[2] = fmaf(h, wa.z, mu[2]);
        ls[0] = fmaf(h, wa.w, ls[0]);
        ls[1] = fmaf(h, wb.x, ls[1]);
        ls[2] = fmaf(h, wb.y, ls[2]);
    }

    // Outputs: z | mu_xz | log_sigma_xz | mu_zx | log_t_zx | mu_z | log_t_z
    out[2 * p + 0] = z0;
    out[2 * p + 1] = z1;
    out[2 * NP + 3 * p + 0] = mu[0];
    out[2 * NP + 3 * p + 1] = mu[1];
    out[2 * NP + 3 * p + 2] = mu[2];
    out[5 * NP + 3 * p + 0] = ls[0];
    out[5 * NP + 3 * p + 1] = ls[1];
    out[5 * NP + 3 * p + 2] = ls[2];
    out[11 * NP + 2 * p + 0] = b_muz[0];
    out[11 * NP + 2 * p + 1] = b_muz[1];
    out[13 * NP + p] = b_ltz[0];
}

extern "C" void kernel_launch(void* const* d_in, const int* in_sizes, int n_in,
                              void* d_out, int out_size)
{
    const float* x     = (const float*)d_in[0];
    const float* We1   = (const float*)d_in[1];
    const float* be1   = (const float*)d_in[2];
    const float* We2   = (const float*)d_in[3];
    const float* be2   = (const float*)d_in[4];
    const float* Wmu   = (const float*)d_in[5];
    const float* bmu   = (const float*)d_in[6];
    const float* Wlt   = (const float*)d_in[7];
    const float* blt   = (const float*)d_in[8];
    const float* Wd1   = (const float*)d_in[9];
    const float* bd1   = (const float*)d_in[10];
    const float* Wdmu  = (const float*)d_in[11];
    const float* bdmu  = (const float*)d_in[12];
    const float* Wds   = (const float*)d_in[13];
    const float* bds   = (const float*)d_in[14];
    const float* b_muz = (const float*)d_in[15];
    const float* b_ltz = (const float*)d_in[16];
    const float* noise = (const float*)d_in[17];
    float* out = (float*)d_out;

    const size_t smem = (size_t)(10800 + 128 * (HIDN + 1)) * sizeof(float); // ~94.9 KB
    cudaFuncSetAttribute(encoder_kernel,
                         cudaFuncAttributeMaxDynamicSharedMemorySize, (int)smem);

    encoder_kernel<<<NP / 128, 128, smem>>>(x, We1, be1, We2, be2,
                                            Wmu, bmu, Wlt, blt, out);
    sde_kernel<<<NP / 128, 128>>>(Wd1, bd1, Wdmu, bdmu, Wds, bds,
                                  b_muz, b_ltz, noise, out);
}